// round 12
// baseline (speedup 1.0000x reference)
#include <cuda_runtime.h>
#include <cuda_bf16.h>

// Single-pass WKV scan, decoupled lookback, intra-block sub-segment scan.
// R11: SUBSEG 16 -> 8 to cut regs (~62 -> ~42) and raise residency from
// 4 to 6 blocks/SM (RF was the binding cap: 62*1024 ~ 64K regs). More
// co-resident blocks decorrelate load/compose phases -> higher DRAM%.
//
// Block = 256 threads = 32 channels x 8 sub-segments of 8 timesteps
//   -> block covers 64 timesteps; chain NSEG = 32 hops (hidden: ~1.7
//      hops per wave across 18.4 waves).
// Thread-local normalized scan (decay product cancels in out = b/a):
//   cw_i = sum w ; e_i = exp(k_i - cw_i) ; ah_i = sum e ; bh_i = sum e*v
// Sub-segment map: a_out = P*a_in + P*aa, P = exp(cw_end). Warp 0 composes
// the 8 maps; exclusive prefixes are linear in the incoming state, so all
// heavy work precedes the lookback wait. Flags self-cleaning.

#define BATCH  16
#define TLEN   2048
#define DIM    1024
#define CHAN   (BATCH * DIM)       // 16384
#define NCH    32                  // channels per block
#define NSUB   8                   // sub-segments per block
#define SUBSEG 8                   // timesteps per thread
#define SEGT   (NSUB * SUBSEG)     // 64 timesteps per block
#define NSEG   (TLEN / SEGT)       // 32 global segments
#define NCG    (CHAN / NCH)        // 512 channel groups
#define BLKT   (NCH * NSUB)        // 256 threads

__device__ float    g_prefA[NSEG * CHAN];
__device__ float    g_prefB[NSEG * CHAN];
__device__ unsigned g_flag [NSEG * NCG];   // zero-init; self-cleaning

__global__ __launch_bounds__(BLKT, 6)
void wkv_fused(const float* __restrict__ K,
               const float* __restrict__ V,
               const float* __restrict__ W,
               float* __restrict__ O) {
    const int s    = blockIdx.x / NCG;      // global segment (segment-major)
    const int cg   = blockIdx.x % NCG;      // channel group
    const int tid  = threadIdx.x;
    const int lane = tid & (NCH - 1);       // channel within group
    const int sub  = tid >> 5;              // sub-segment 0..7
    const int c    = cg * NCH + lane;       // global channel
    const int b    = c >> 10;               // / DIM
    const int d    = c & (DIM - 1);         // % DIM

    __shared__ float sP [NSUB][NCH], sQa[NSUB][NCH], sQb[NSUB][NCH];
    __shared__ float sBt[NSUB][NCH], sAl[NSUB][NCH], sBl[NSUB][NCH];
    __shared__ float sA0[NCH], sB0[NCH];

    const int t0 = s * SEGT + sub * SUBSEG;
    const size_t base = (size_t)b * TLEN * DIM + (size_t)t0 * DIM + d;
    const float* kp = K + base;
    const float* vp = V + base;
    const float* wp = W + base;
    float*       op = O + base;

    // ---- front-batched loads: 24 independent LDGs before any compute ----
    float wb[SUBSEG], kb[SUBSEG], vb[SUBSEG];
#pragma unroll
    for (int i = 0; i < SUBSEG; ++i) wb[i] = wp[i * DIM];
#pragma unroll
    for (int i = 0; i < SUBSEG; ++i) kb[i] = kp[i * DIM];
#pragma unroll
    for (int i = 0; i < SUBSEG; ++i) vb[i] = vp[i * DIM];

    // ---- normalized local scan; reuse kb -> ah, vb -> bh in place ----
    float cw = 0.0f, aa = 0.0f, bb = 0.0f;
#pragma unroll
    for (int i = 0; i < SUBSEG; ++i) {
        cw += wb[i];
        const float e = __expf(kb[i] - cw);
        aa += e;
        bb = fmaf(e, vb[i], bb);
        kb[i] = aa;      // ah
        vb[i] = bb;      // bh
    }
    const float P = __expf(cw);
    sP [sub][lane] = P;
    sQa[sub][lane] = P * aa;
    sQb[sub][lane] = P * bb;
    __syncthreads();

    // ---- warp 0: compose 8 maps per channel, lookback, publish ----
    if (tid < NCH) {
        float beta = 1.0f, alA = 0.0f, alB = 0.0f;
#pragma unroll
        for (int j = 0; j < NSUB; ++j) {
            sBt[j][tid] = beta;
            sAl[j][tid] = alA;
            sBl[j][tid] = alB;
            const float p = sP[j][tid];
            beta = p * beta;
            alA  = fmaf(p, alA, sQa[j][tid]);
            alB  = fmaf(p, alB, sQb[j][tid]);
        }

        float a0 = 0.0f, b0 = 0.0f;
        if (s > 0) {
            volatile unsigned* f = &g_flag[(s - 1) * NCG + cg];
            while (*f == 0u) __nanosleep(40);
            __threadfence();   // acquire
            a0 = g_prefA[(size_t)(s - 1) * CHAN + c];
            b0 = g_prefB[(size_t)(s - 1) * CHAN + c];
            if (tid == 0) atomicExch(&g_flag[(s - 1) * NCG + cg], 0u); // self-clean
        }
        sA0[tid] = a0;
        sB0[tid] = b0;

        if (s < NSEG - 1) {    // last segment has no consumer
            g_prefA[(size_t)s * CHAN + c] = fmaf(beta, a0, alA);
            g_prefB[(size_t)s * CHAN + c] = fmaf(beta, b0, alB);
            __threadfence();   // release
            __syncwarp(0xFFFFFFFFu);
            if (tid == 0) atomicExch(&g_flag[s * NCG + cg], 1u);
        }
    }
    __syncthreads();

    // ---- outputs ----
    const float beta = sBt[sub][lane];
    const float A_in = fmaf(beta, sA0[lane], sAl[sub][lane]);
    const float B_in = fmaf(beta, sB0[lane], sBl[sub][lane]);
#pragma unroll
    for (int i = 0; i < SUBSEG; ++i)
        op[i * DIM] = __fdividef(B_in + vb[i], A_in + kb[i]);
}

extern "C" void kernel_launch(void* const* d_in, const int* in_sizes, int n_in,
                              void* d_out, int out_size) {
    const float* K = (const float*)d_in[0];
    const float* V = (const float*)d_in[1];
    const float* W = (const float*)d_in[2];
    float*       O = (float*)d_out;

    wkv_fused<<<NSEG * NCG, BLKT>>>(K, V, W, O);   // 16384 blocks, segment-major
}

// round 13
// speedup vs baseline: 1.0574x; 1.0574x over previous
#include <cuda_runtime.h>
#include <cuda_bf16.h>

// Single-pass WKV scan, decoupled lookback, intra-block sub-segment scan.
// R12 consolidation of best-measured pieces:
//   - R6 block shape + interleaved load-scan (best DRAM%: 74.2)
//   - R9 self-cleaning flags (no reset kernel)
//   - __ldcs / __stcs streaming hints (all bulk data is touch-once)
//
// Block = 256 threads = 32 channels x 8 sub-segments of 16 timesteps
//   -> block covers 128 timesteps; chain NSEG = 16 hops (hidden across
//      ~14 waves of the 8192-block segment-major grid).
// Thread-local normalized scan (decay product cancels in out = b/a):
//   cw_i = sum w ; e_i = exp(k_i - cw_i) ; ah_i = sum e ; bh_i = sum e*v
// Sub-segment affine map: a_out = P*a_in + P*aa, P = exp(cw_end).
// Warp 0 composes the 8 maps per channel; exclusive prefixes are linear in
// the incoming state, so all heavy work precedes the lookback wait.

#define BATCH  16
#define TLEN   2048
#define DIM    1024
#define CHAN   (BATCH * DIM)       // 16384
#define NCH    32                  // channels per block
#define NSUB   8                   // sub-segments per block
#define SUBSEG 16                  // timesteps per thread
#define SEGT   (NSUB * SUBSEG)     // 128 timesteps per block
#define NSEG   (TLEN / SEGT)       // 16 global segments
#define NCG    (CHAN / NCH)        // 512 channel groups
#define BLKT   (NCH * NSUB)        // 256 threads

__device__ float    g_prefA[NSEG * CHAN];
__device__ float    g_prefB[NSEG * CHAN];
__device__ unsigned g_flag [NSEG * NCG];   // zero-init; self-cleaning

__global__ __launch_bounds__(BLKT, 4)
void wkv_fused(const float* __restrict__ K,
               const float* __restrict__ V,
               const float* __restrict__ W,
               float* __restrict__ O) {
    const int s    = blockIdx.x / NCG;      // global segment (segment-major)
    const int cg   = blockIdx.x % NCG;      // channel group
    const int tid  = threadIdx.x;
    const int lane = tid & (NCH - 1);       // channel within group
    const int sub  = tid >> 5;              // sub-segment 0..7
    const int c    = cg * NCH + lane;       // global channel
    const int b    = c >> 10;               // / DIM
    const int d    = c & (DIM - 1);         // % DIM

    __shared__ float sP [NSUB][NCH], sQa[NSUB][NCH], sQb[NSUB][NCH];
    __shared__ float sBt[NSUB][NCH], sAl[NSUB][NCH], sBl[NSUB][NCH];
    __shared__ float sA0[NCH], sB0[NCH];

    const int t0 = s * SEGT + sub * SUBSEG;
    const size_t base = (size_t)b * TLEN * DIM + (size_t)t0 * DIM + d;
    const float* kp = K + base;
    const float* vp = V + base;
    const float* wp = W + base;
    float*       op = O + base;

    // ---- thread-local normalized scan, interleaved loads (R6 body) ----
    float ah[SUBSEG], bh[SUBSEG];
    float cw = 0.0f, aa = 0.0f, bb = 0.0f;
#pragma unroll
    for (int i = 0; i < SUBSEG; ++i) {
        const float ki = __ldcs(kp + i * DIM);
        const float vi = __ldcs(vp + i * DIM);
        const float wi = __ldcs(wp + i * DIM);
        cw += wi;
        const float e = __expf(ki - cw);
        aa += e;
        bb = fmaf(e, vi, bb);
        ah[i] = aa;
        bh[i] = bb;
    }
    const float P = __expf(cw);
    sP [sub][lane] = P;
    sQa[sub][lane] = P * aa;
    sQb[sub][lane] = P * bb;
    __syncthreads();

    // ---- warp 0: compose 8 maps per channel, lookback, publish ----
    if (tid < NCH) {
        float beta = 1.0f, alA = 0.0f, alB = 0.0f;
#pragma unroll
        for (int j = 0; j < NSUB; ++j) {
            sBt[j][tid] = beta;
            sAl[j][tid] = alA;
            sBl[j][tid] = alB;
            const float p = sP[j][tid];
            beta = p * beta;
            alA  = fmaf(p, alA, sQa[j][tid]);
            alB  = fmaf(p, alB, sQb[j][tid]);
        }

        float a0 = 0.0f, b0 = 0.0f;
        if (s > 0) {
            volatile unsigned* f = &g_flag[(s - 1) * NCG + cg];
            while (*f == 0u) __nanosleep(40);
            __threadfence();   // acquire
            a0 = g_prefA[(size_t)(s - 1) * CHAN + c];
            b0 = g_prefB[(size_t)(s - 1) * CHAN + c];
            if (tid == 0) atomicExch(&g_flag[(s - 1) * NCG + cg], 0u); // self-clean
        }
        sA0[tid] = a0;
        sB0[tid] = b0;

        if (s < NSEG - 1) {    // last segment has no consumer
            g_prefA[(size_t)s * CHAN + c] = fmaf(beta, a0, alA);
            g_prefB[(size_t)s * CHAN + c] = fmaf(beta, b0, alB);
            __threadfence();   // release
            __syncwarp(0xFFFFFFFFu);
            if (tid == 0) atomicExch(&g_flag[s * NCG + cg], 1u);
        }
    }
    __syncthreads();

    // ---- outputs (streaming stores) ----
    const float beta = sBt[sub][lane];
    const float A_in = fmaf(beta, sA0[lane], sAl[sub][lane]);
    const float B_in = fmaf(beta, sB0[lane], sBl[sub][lane]);
#pragma unroll
    for (int i = 0; i < SUBSEG; ++i)
        __stcs(op + i * DIM, __fdividef(B_in + bh[i], A_in + ah[i]));
}

extern "C" void kernel_launch(void* const* d_in, const int* in_sizes, int n_in,
                              void* d_out, int out_size) {
    const float* K = (const float*)d_in[0];
    const float* V = (const float*)d_in[1];
    const float* W = (const float*)d_in[2];
    float*       O = (float*)d_out;

    wkv_fused<<<NSEG * NCG, BLKT>>>(K, V, W, O);   // 8192 blocks, segment-major
}

// round 14
// speedup vs baseline: 1.0897x; 1.0305x over previous
#include <cuda_runtime.h>
#include <cuda_bf16.h>

// Single-pass WKV scan, decoupled lookback, intra-block sub-segment scan.
// R13 = exact best-measured combination:
//   - R6 kernel body verbatim (interleaved load-scan; best DRAM 74.2%,
//     87.3us kernel time)
//   - R9 self-cleaning flags (no reset kernel; consumer resets, last
//     segment never publishes -> flags all-zero after every graph replay)
//   - DEFAULT cache operators (R12 showed __ldcs/__stcs cost ~3us here)
//
// Block = 256 threads = 32 channels x 8 sub-segments of 16 timesteps
//   -> block covers 128 timesteps; chain NSEG = 16 hops, hidden across
//      ~14 waves of the segment-major grid.
// Thread-local normalized scan (decay product cancels in out = b/a):
//   cw_i = sum w ; e_i = exp(k_i - cw_i) ; ah_i = sum e ; bh_i = sum e*v
// Sub-segment affine map: a_out = P*a_in + P*aa, P = exp(cw_end).
// Warp 0 composes the 8 maps per channel; exclusive prefixes are linear in
// the incoming state, so all heavy work precedes the lookback wait.

#define BATCH  16
#define TLEN   2048
#define DIM    1024
#define CHAN   (BATCH * DIM)       // 16384
#define NCH    32                  // channels per block
#define NSUB   8                   // sub-segments per block
#define SUBSEG 16                  // timesteps per thread
#define SEGT   (NSUB * SUBSEG)     // 128 timesteps per block
#define NSEG   (TLEN / SEGT)       // 16 global segments
#define NCG    (CHAN / NCH)        // 512 channel groups
#define BLKT   (NCH * NSUB)        // 256 threads

__device__ float    g_prefA[NSEG * CHAN];
__device__ float    g_prefB[NSEG * CHAN];
__device__ unsigned g_flag [NSEG * NCG];   // zero-init; self-cleaning

__global__ __launch_bounds__(BLKT, 4)
void wkv_fused(const float* __restrict__ K,
               const float* __restrict__ V,
               const float* __restrict__ W,
               float* __restrict__ O) {
    const int s    = blockIdx.x / NCG;      // global segment (segment-major)
    const int cg   = blockIdx.x % NCG;      // channel group
    const int tid  = threadIdx.x;
    const int lane = tid & (NCH - 1);       // channel within group
    const int sub  = tid >> 5;              // sub-segment 0..7
    const int c    = cg * NCH + lane;       // global channel
    const int b    = c >> 10;               // / DIM
    const int d    = c & (DIM - 1);         // % DIM

    __shared__ float sP [NSUB][NCH], sQa[NSUB][NCH], sQb[NSUB][NCH];
    __shared__ float sBt[NSUB][NCH], sAl[NSUB][NCH], sBl[NSUB][NCH];
    __shared__ float sA0[NCH], sB0[NCH];

    const int t0 = s * SEGT + sub * SUBSEG;
    const size_t base = (size_t)b * TLEN * DIM + (size_t)t0 * DIM + d;
    const float* kp = K + base;
    const float* vp = V + base;
    const float* wp = W + base;
    float*       op = O + base;

    // ---- thread-local normalized scan, interleaved loads (R6 body) ----
    float ah[SUBSEG], bh[SUBSEG];
    float cw = 0.0f, aa = 0.0f, bb = 0.0f;
#pragma unroll
    for (int i = 0; i < SUBSEG; ++i) {
        const float ki = kp[i * DIM];
        const float vi = vp[i * DIM];
        const float wi = wp[i * DIM];
        cw += wi;
        const float e = __expf(ki - cw);
        aa += e;
        bb = fmaf(e, vi, bb);
        ah[i] = aa;
        bh[i] = bb;
    }
    const float P = __expf(cw);
    sP [sub][lane] = P;
    sQa[sub][lane] = P * aa;
    sQb[sub][lane] = P * bb;
    __syncthreads();

    // ---- warp 0: compose 8 maps per channel, lookback, publish ----
    if (tid < NCH) {
        float beta = 1.0f, alA = 0.0f, alB = 0.0f;
#pragma unroll
        for (int j = 0; j < NSUB; ++j) {
            sBt[j][tid] = beta;
            sAl[j][tid] = alA;
            sBl[j][tid] = alB;
            const float p = sP[j][tid];
            beta = p * beta;
            alA  = fmaf(p, alA, sQa[j][tid]);
            alB  = fmaf(p, alB, sQb[j][tid]);
        }

        float a0 = 0.0f, b0 = 0.0f;
        if (s > 0) {
            volatile unsigned* f = &g_flag[(s - 1) * NCG + cg];
            while (*f == 0u) __nanosleep(40);
            __threadfence();   // acquire
            a0 = g_prefA[(size_t)(s - 1) * CHAN + c];
            b0 = g_prefB[(size_t)(s - 1) * CHAN + c];
            if (tid == 0) atomicExch(&g_flag[(s - 1) * NCG + cg], 0u); // self-clean
        }
        sA0[tid] = a0;
        sB0[tid] = b0;

        if (s < NSEG - 1) {    // last segment has no consumer
            g_prefA[(size_t)s * CHAN + c] = fmaf(beta, a0, alA);
            g_prefB[(size_t)s * CHAN + c] = fmaf(beta, b0, alB);
            __threadfence();   // release
            __syncwarp(0xFFFFFFFFu);
            if (tid == 0) atomicExch(&g_flag[s * NCG + cg], 1u);
        }
    }
    __syncthreads();

    // ---- outputs ----
    const float beta = sBt[sub][lane];
    const float A_in = fmaf(beta, sA0[lane], sAl[sub][lane]);
    const float B_in = fmaf(beta, sB0[lane], sBl[sub][lane]);
#pragma unroll
    for (int i = 0; i < SUBSEG; ++i)
        op[i * DIM] = __fdividef(B_in + bh[i], A_in + ah[i]);
}

extern "C" void kernel_launch(void* const* d_in, const int* in_sizes, int n_in,
                              void* d_out, int out_size) {
    const float* K = (const float*)d_in[0];
    const float* V = (const float*)d_in[1];
    const float* W = (const float*)d_in[2];
    float*       O = (float*)d_out;

    wkv_fused<<<NSEG * NCG, BLKT>>>(K, V, W, O);   // 8192 blocks, segment-major
}